// round 1
// baseline (speedup 1.0000x reference)
#include <cuda_runtime.h>
#include <cuda_bf16.h>

// Problem constants
#define S_LEN 2048
#define B_SZ  16
#define H_DIM 1024

// Scratch: energy[B][H]  (no cudaMalloc allowed)
__device__ float g_energy[B_SZ * H_DIM];

// ---------------------------------------------------------------------------
// Kernel 1: energy[b][h] = sum_j state[b][j] * W[h][j] + bias[h]
// state = last_decoder_state[0,0] = first B*H floats of lds.
// grid = H blocks, block = 512 threads = 16 warps; warp w handles b=w.
// W row (4 KB) is read once per block and shared across warps via L1.
// ---------------------------------------------------------------------------
__global__ void energy_kernel(const float* __restrict__ lds,
                              const float* __restrict__ W,
                              const float* __restrict__ bias)
{
    const int h    = blockIdx.x;
    const int warp = threadIdx.x >> 5;   // = b
    const int lane = threadIdx.x & 31;

    const float4* wrow = reinterpret_cast<const float4*>(W + (size_t)h * H_DIM);
    const float4* st   = reinterpret_cast<const float4*>(lds + (size_t)warp * H_DIM);

    float acc = 0.f;
    #pragma unroll
    for (int i = 0; i < H_DIM / 4 / 32; ++i) {   // 8 iterations
        float4 a = wrow[lane + i * 32];
        float4 s = st[lane + i * 32];
        acc += a.x * s.x + a.y * s.y + a.z * s.z + a.w * s.w;
    }
    #pragma unroll
    for (int off = 16; off > 0; off >>= 1)
        acc += __shfl_xor_sync(0xFFFFFFFF, acc, off);

    if (lane == 0)
        g_energy[warp * H_DIM + h] = acc + bias[h];
}

// ---------------------------------------------------------------------------
// Kernel 2 (the HBM-bound one):
// scores[s][b] = sum_h enc[s][b][h] * energy[b][h]
// One block per row (s*B+b). 128 threads, each 2x float4 = 8 floats.
// Writes raw scores into d_out laid out [S][B] (matches output layout).
// ---------------------------------------------------------------------------
__global__ void __launch_bounds__(128, 16)
score_kernel(const float* __restrict__ enc, float* __restrict__ out)
{
    const int row = blockIdx.x;          // s*B + b
    const int b   = row & (B_SZ - 1);
    const int t   = threadIdx.x;

    const float4* e = reinterpret_cast<const float4*>(enc + (size_t)row * H_DIM);
    const float4* g = reinterpret_cast<const float4*>(g_energy + (size_t)b * H_DIM);

    float acc = 0.f;
    #pragma unroll
    for (int i = 0; i < 2; ++i) {
        float4 a = e[t + i * 128];
        float4 w = g[t + i * 128];
        acc += a.x * w.x + a.y * w.y + a.z * w.z + a.w * w.w;
    }

    // block reduce: 4 warps
    #pragma unroll
    for (int off = 16; off > 0; off >>= 1)
        acc += __shfl_xor_sync(0xFFFFFFFF, acc, off);

    __shared__ float red[4];
    const int warp = t >> 5;
    const int lane = t & 31;
    if (lane == 0) red[warp] = acc;
    __syncthreads();
    if (t == 0)
        out[row] = red[0] + red[1] + red[2] + red[3];
}

// ---------------------------------------------------------------------------
// Kernel 3: softmax over S (axis 0) per batch column b, in place on d_out.
// grid = B blocks of 256 threads; each thread holds 8 values in registers.
// ---------------------------------------------------------------------------
__global__ void softmax_kernel(float* __restrict__ out)
{
    const int b = blockIdx.x;
    const int t = threadIdx.x;
    const int VPT = S_LEN / 256;   // 8

    float v[VPT];
    float mx = -3.402823466e38f;
    #pragma unroll
    for (int i = 0; i < VPT; ++i) {
        v[i] = out[(size_t)(t + i * 256) * B_SZ + b];
        mx = fmaxf(mx, v[i]);
    }

    // block max
    __shared__ float sm[8];
    #pragma unroll
    for (int off = 16; off > 0; off >>= 1)
        mx = fmaxf(mx, __shfl_xor_sync(0xFFFFFFFF, mx, off));
    const int warp = t >> 5, lane = t & 31;
    if (lane == 0) sm[warp] = mx;
    __syncthreads();
    if (warp == 0) {
        float m = (lane < 8) ? sm[lane] : -3.402823466e38f;
        #pragma unroll
        for (int off = 4; off > 0; off >>= 1)
            m = fmaxf(m, __shfl_xor_sync(0xFFFFFFFF, m, off));
        if (lane == 0) sm[0] = m;
    }
    __syncthreads();
    mx = sm[0];
    __syncthreads();

    // exp + block sum
    float sum = 0.f;
    #pragma unroll
    for (int i = 0; i < VPT; ++i) {
        v[i] = __expf(v[i] - mx);
        sum += v[i];
    }
    #pragma unroll
    for (int off = 16; off > 0; off >>= 1)
        sum += __shfl_xor_sync(0xFFFFFFFF, sum, off);
    if (lane == 0) sm[warp] = sum;
    __syncthreads();
    if (warp == 0) {
        float s = (lane < 8) ? sm[lane] : 0.f;
        #pragma unroll
        for (int off = 4; off > 0; off >>= 1)
            s += __shfl_xor_sync(0xFFFFFFFF, s, off);
        if (lane == 0) sm[0] = s;
    }
    __syncthreads();
    const float inv = 1.0f / sm[0];

    #pragma unroll
    for (int i = 0; i < VPT; ++i)
        out[(size_t)(t + i * 256) * B_SZ + b] = v[i] * inv;
}

// ---------------------------------------------------------------------------
extern "C" void kernel_launch(void* const* d_in, const int* in_sizes, int n_in,
                              void* d_out, int out_size)
{
    const float* enc  = (const float*)d_in[0];  // [S,B,H]
    const float* lds  = (const float*)d_in[1];  // [2,1,B,H]
    const float* W    = (const float*)d_in[2];  // [H,H]
    const float* bias = (const float*)d_in[3];  // [H]
    float* out = (float*)d_out;                 // [1,1,S,B] == [S,B]

    energy_kernel<<<H_DIM, 512>>>(lds, W, bias);
    score_kernel<<<S_LEN * B_SZ, 128>>>(enc, out);
    softmax_kernel<<<B_SZ, 256>>>(out);
}